// round 6
// baseline (speedup 1.0000x reference)
#include <cuda_runtime.h>
#include <math.h>
#include <cstdint>

#define N_TOK   8192
#define DM      256
#define NE      16
#define NVIEW   3
#define TOPK    4
#define HID     1024
#define TM      64

// ---- ffn smem layout (float indices) ----
#define XP_F    0           // Xperm A-frag order: 4mt x 32ks x 32lane x 4 = 16384
#define WB_F    16384       // weight double buffer: 2 x (W1 8192 + W2 8192) = 32768
#define HP_F    49152       // Hperm A-frag order: 4mt x 4ks x 32lane x 4 = 2048
#define B1_F    51200       // 1024
#define B2_F    52224       // 256
#define TOK_F   52480       // 64 ints
#define GATE_F  52544       // 64
#define SMEM_FLOATS 52608
#define SMEM_BYTES  (SMEM_FLOATS * 4)    // 210432

// ---------------- device scratch ----------------
__device__ int   g_cnt [NVIEW * NE];
__device__ int   g_tok [NVIEW * NE * N_TOK];
__device__ float g_gate[NVIEW * NE * N_TOK];
__device__ float g_w1p [NE * DM * HID];   // W1, tf32-rounded, B-frag order
__device__ float g_w2p [NE * HID * DM];   // W2, tf32-rounded, B-frag order

// ---------------- helpers ----------------
__device__ __forceinline__ float tf32r(float x) {
    asm("cvt.rna.tf32.f32 %0, %1;" : "=f"(x) : "f"(x));
    return x;
}
__device__ __forceinline__ float4 tf32r4(float4 v) {
    v.x = tf32r(v.x); v.y = tf32r(v.y); v.z = tf32r(v.z); v.w = tf32r(v.w);
    return v;
}
__device__ __forceinline__ float d4(float4 a, float4 b) {
    return a.x * b.x + a.y * b.y + a.z * b.z + a.w * b.w;
}
__device__ __forceinline__ float wredsum(float x) {
#pragma unroll
    for (int o = 16; o > 0; o >>= 1) x += __shfl_xor_sync(0xffffffffu, x, o);
    return x;
}
__device__ __forceinline__ float gelu_exact(float x) {
    return 0.5f * x * (1.0f + erff(x * 0.70710678118654752440f));
}
__device__ __forceinline__ uint32_t smem_u32(const void* p) {
    uint32_t a;
    asm("{ .reg .u64 t; cvta.to.shared.u64 t, %1; cvt.u32.u64 %0, t; }"
        : "=r"(a) : "l"(p));
    return a;
}
__device__ __forceinline__ void cp_async16(uint32_t dst, const void* src) {
    asm volatile("cp.async.cg.shared.global [%0], [%1], 16;"
                 :: "r"(dst), "l"(src));
}
// m16n8k8 tf32 mma: D += A*B
__device__ __forceinline__ void mma8(float4& d, const uint4& a,
                                     uint32_t b0, uint32_t b1) {
    asm volatile(
        "mma.sync.aligned.m16n8k8.row.col.f32.tf32.tf32.f32 "
        "{%0,%1,%2,%3}, {%4,%5,%6,%7}, {%8,%9}, {%0,%1,%2,%3};"
        : "+f"(d.x), "+f"(d.y), "+f"(d.z), "+f"(d.w)
        : "r"(a.x), "r"(a.y), "r"(a.z), "r"(a.w), "r"(b0), "r"(b1));
}

// ---------------- kernel 0: prep (unchanged from R5) ----------------
__global__ void prep_kernel(const float* __restrict__ W1,
                            const float* __restrict__ W2) {
    __shared__ float s[256 * 36];
    int tid = threadIdx.x, b = blockIdx.x;
    if (b == 0 && tid < NVIEW * NE) g_cnt[tid] = 0;
    if (b < 512) {
        int e = b >> 5, jc = b & 31;
        for (int i = tid; i < 2048; i += 256) {
            int d = i >> 3, j4 = i & 7;
            float4 v = ((const float4*)(W1 + ((size_t)e * DM + d) * HID + jc * 32))[j4];
            *(float4*)&s[d * 36 + j4 * 4] = tf32r4(v);
        }
        __syncthreads();
        float4* dst = (float4*)g_w1p + (size_t)(e * 32 + jc) * 2048;
        for (int o = tid; o < 2048; o += 256) {
            int nt = o >> 9, kp = (o >> 5) & 15, ln = o & 31;
            int tig = ln & 3, g = ln >> 2;
            int jl = nt * 8 + g;
            float4 v;
            v.x = s[(16 * kp + tig) * 36 + jl];
            v.y = s[(16 * kp + tig + 4) * 36 + jl];
            v.z = s[(16 * kp + 8 + tig) * 36 + jl];
            v.w = s[(16 * kp + 8 + tig + 4) * 36 + jl];
            dst[o] = v;
        }
    } else {
        int e = (b - 512) >> 5, jc = (b - 512) & 31;
        for (int i = tid; i < 2048; i += 256) {
            int rl = i >> 6, n4 = i & 63;
            float4 v = ((const float4*)(W2 + ((size_t)e * HID + jc * 32 + rl) * DM))[n4];
            *(float4*)&s[rl * 260 + n4 * 4] = tf32r4(v);
        }
        __syncthreads();
        float4* dst = (float4*)g_w2p + (size_t)(e * 32 + jc) * 2048;
        for (int o = tid; o < 2048; o += 256) {
            int nt = o >> 6, kp = (o >> 5) & 1, ln = o & 31;
            int tig = ln & 3, g = ln >> 2;
            int n = nt * 8 + g;
            float4 v;
            v.x = s[(16 * kp + tig) * 260 + n];
            v.y = s[(16 * kp + tig + 4) * 260 + n];
            v.z = s[(16 * kp + 8 + tig) * 260 + n];
            v.w = s[(16 * kp + 8 + tig + 4) * 260 + n];
            dst[o] = v;
        }
    }
}

// ---------------- kernel 1: router (bit-exact fp32 sequence, unchanged) ------
__global__ void router_kernel(const float* __restrict__ v0,
                              const float* __restrict__ v1,
                              const float* __restrict__ v2,
                              const float* __restrict__ rw,
                              const float* __restrict__ keys) {
    int vi   = blockIdx.y;
    int warp = threadIdx.x >> 5;
    int lane = threadIdx.x & 31;
    int tok  = blockIdx.x * 8 + warp;
    if (tok >= N_TOK) return;

    const float* vbase = (vi == 0) ? v0 : ((vi == 1) ? v1 : v2);
    const float* v = vbase + tok * DM;

    float4 a = ((const float4*)v)[lane];
    float4 b = ((const float4*)v)[lane + 32];

    float vv = wredsum(d4(a, a) + d4(b, b));

    const float* rwv = rw + (size_t)vi * NE * DM;
    float lg[NE];
#pragma unroll
    for (int e = 0; e < NE; e++) {
        const float4* kp = (const float4*)(keys + e * DM);
        const float4* rp = (const float4*)(rwv + e * DM);
        float4 k1 = kp[lane], k2 = kp[lane + 32];
        float4 r1 = rp[lane], r2 = rp[lane + 32];
        float dk = wredsum(d4(a, k1) + d4(b, k2));
        float dr = wredsum(d4(a, r1) + d4(b, r2));
        float kk = wredsum(d4(k1, k1) + d4(k2, k2));
        float sq = (vv + kk) - 2.0f * dk;
        lg[e] = (-sq) + dr;
    }

    if (lane == 0) {
        unsigned chosen = 0;
        float tv[TOPK];
        int   ti[TOPK];
#pragma unroll
        for (int k = 0; k < TOPK; k++) {
            float m = -1e30f; int mi = 0;
#pragma unroll
            for (int e = 0; e < NE; e++) {
                if (!((chosen >> e) & 1u) && lg[e] > m) { m = lg[e]; mi = e; }
            }
            tv[k] = m; ti[k] = mi; chosen |= (1u << mi);
        }
        float s = 0.f;
        float ex[TOPK];
#pragma unroll
        for (int k = 0; k < TOPK; k++) { ex[k] = expf(tv[k] - tv[0]); s += ex[k]; }
        float inv = 1.0f / s;
#pragma unroll
        for (int k = 0; k < TOPK; k++) {
            int ge  = vi * NE + ti[k];
            int pos = atomicAdd(&g_cnt[ge], 1);
            g_tok [ge * N_TOK + pos] = tok;
            g_gate[ge * N_TOK + pos] = ex[k] * inv;
        }
    }
}

// ---------------- kernel 2: grouped FFN, smem-staged weights ----------------
extern "C" __global__ void __launch_bounds__(256, 1)
ffn_kernel(const float* __restrict__ v0, const float* __restrict__ v1,
           const float* __restrict__ v2,
           const float* __restrict__ b1, const float* __restrict__ b2,
           float* __restrict__ out) {
    extern __shared__ float sm[];
    int tid = threadIdx.x, wid = tid >> 5, lane = tid & 31;
    int vi = blockIdx.z, e = blockIdx.y, g0 = vi * NE + e;
    int cnt = g_cnt[g0];
    int t0 = blockIdx.x * TM;
    if (t0 >= cnt) return;
    int rows = min(TM, cnt - t0);

    int*   s_tok  = (int*)&sm[TOK_F];
    float* s_gate = &sm[GATE_F];
    if (tid < TM) {
        int idx = t0 + tid;
        s_tok [tid] = (idx < cnt) ? g_tok [g0 * N_TOK + idx] : 0;
        s_gate[tid] = (idx < cnt) ? g_gate[g0 * N_TOK + idx] : 0.0f;
    }
    for (int i = tid; i < HID; i += 256) sm[B1_F + i] = b1[(size_t)e * HID + i];
    for (int i = tid; i < DM;  i += 256) sm[B2_F + i] = b2[(size_t)e * DM + i];
    __syncthreads();

    const float* V = (vi == 0) ? v0 : ((vi == 1) ? v1 : v2);

    // ---- gather X -> A-fragment-permuted smem (tf32-rna) ----
    for (int i = tid; i < TM * 64; i += 256) {
        int r = i >> 6, c4 = i & 63;
        float4 v = make_float4(0.f, 0.f, 0.f, 0.f);
        if (r < rows) v = tf32r4(((const float4*)(V + (size_t)s_tok[r] * DM))[c4]);
        int mt = r >> 4, pair = (r >> 3) & 1, gg = r & 7;
        int ks = c4 >> 1, q = pair + 2 * (c4 & 1);
        int base = ((mt * 32 + ks) * 32 + gg * 4) * 4 + q;
        sm[XP_F + base     ] = v.x;
        sm[XP_F + base + 4 ] = v.y;
        sm[XP_F + base + 8 ] = v.z;
        sm[XP_F + base + 12] = v.w;
    }

    const uint4* W1Pg = (const uint4*)g_w1p + (size_t)(e * 32) * 2048;
    const uint4* W2Pg = (const uint4*)g_w2p + (size_t)(e * 32) * 2048;
    const uint32_t wbB = smem_u32(&sm[WB_F]);   // byte addr of weight buffers

    // stage chunk 0 into buffer 0
    {
#pragma unroll
        for (int k = 0; k < 8; k++) {
            int i = tid + k * 256;
            cp_async16(wbB + i * 16,         W1Pg + i);
            cp_async16(wbB + 32768 + i * 16, W2Pg + i);
        }
        asm volatile("cp.async.commit_group;");
    }

    const uint4* XP  = (const uint4*)&sm[XP_F];
    const uint4* HPl = (const uint4*)&sm[HP_F];
    const int p2 = wid >> 2, o2 = wid & 3;      // GEMM2 warp grid 2m x 4n
    const int gg = lane >> 2, cc = lane & 3;

    float4 acc[2][8];
#pragma unroll
    for (int i = 0; i < 2; i++)
#pragma unroll
        for (int j = 0; j < 8; j++) acc[i][j] = make_float4(0.f, 0.f, 0.f, 0.f);

#pragma unroll 1
    for (int jc = 0; jc < 32; jc++) {
        int buf = jc & 1;
        asm volatile("cp.async.wait_group 0;" ::: "memory");
        __syncthreads();   // bar A: chunk jc weights visible; buf^1 free; Hperm free

        if (jc < 31) {      // stage chunk jc+1 into the other buffer
            uint32_t db = wbB + (buf ^ 1) * 65536;
            const uint4* s1 = W1Pg + (jc + 1) * 2048;
            const uint4* s2 = W2Pg + (jc + 1) * 2048;
#pragma unroll
            for (int k = 0; k < 8; k++) {
                int i = tid + k * 256;
                cp_async16(db + i * 16,         s1 + i);
                cp_async16(db + 32768 + i * 16, s2 + i);
            }
            asm volatile("cp.async.commit_group;");
        }

        const uint4* w1s = (const uint4*)&sm[WB_F + buf * 16384];
        const uint4* w2s = w1s + 2048;

        // ---- GEMM1 on warps 0,1 (warp tile m32 x n32), K = 256 ----
        if (wid < 2) {
            float4 gacc[2][4];
#pragma unroll
            for (int i = 0; i < 2; i++)
#pragma unroll
                for (int j = 0; j < 4; j++) gacc[i][j] = make_float4(0.f, 0.f, 0.f, 0.f);
            const uint4* xb0 = XP + (2 * wid) * 1024 + lane;
            const uint4* xb1 = xb0 + 1024;
            const uint4* wb  = w1s + lane;
#pragma unroll
            for (int kp = 0; kp < 16; kp++) {
                uint4 a0l = xb0[(2 * kp) * 32], a0h = xb0[(2 * kp + 1) * 32];
                uint4 a1l = xb1[(2 * kp) * 32], a1h = xb1[(2 * kp + 1) * 32];
#pragma unroll
                for (int nt = 0; nt < 4; nt++) {
                    uint4 bb = wb[nt * 512 + kp * 32];
                    mma8(gacc[0][nt], a0l, bb.x, bb.y);
                    mma8(gacc[0][nt], a0h, bb.z, bb.w);
                    mma8(gacc[1][nt], a1l, bb.x, bb.y);
                    mma8(gacc[1][nt], a1h, bb.z, bb.w);
                }
            }
            // ---- bias + exact GELU -> Hperm (A-frag order, tf32-rna) ----
#pragma unroll
            for (int mi = 0; mi < 2; mi++) {
                int mt = 2 * wid + mi;
#pragma unroll
                for (int nt = 0; nt < 4; nt++) {
                    int c0 = nt * 8 + 2 * cc;
                    float bx = sm[B1_F + jc * 32 + c0];
                    float by = sm[B1_F + jc * 32 + c0 + 1];
                    float4 v = gacc[mi][nt];
                    int base = ((mt * 4 + nt) * 32 + gg * 4) * 4
                             + 2 * (cc >> 1) + 8 * (cc & 1);
                    sm[HP_F + base    ] = tf32r(gelu_exact(v.x + bx));
                    sm[HP_F + base + 4] = tf32r(gelu_exact(v.y + by));
                    sm[HP_F + base + 1] = tf32r(gelu_exact(v.z + bx));
                    sm[HP_F + base + 5] = tf32r(gelu_exact(v.w + by));
                }
            }
        }
        __syncthreads();   // bar B: Hperm ready

        // ---- GEMM2: acc += H[64,32] @ W2c[32,256] (all 8 warps) ----
        const uint4* w2b = w2s + o2 * 512 + lane;
#pragma unroll
        for (int kp = 0; kp < 2; kp++) {
            uint4 h00 = HPl[((2 * p2) * 4 + 2 * kp) * 32 + lane];
            uint4 h01 = HPl[((2 * p2) * 4 + 2 * kp + 1) * 32 + lane];
            uint4 h10 = HPl[((2 * p2 + 1) * 4 + 2 * kp) * 32 + lane];
            uint4 h11 = HPl[((2 * p2 + 1) * 4 + 2 * kp + 1) * 32 + lane];
#pragma unroll
            for (int nt = 0; nt < 8; nt++) {
                uint4 bb = w2b[(nt * 2 + kp) * 32];
                mma8(acc[0][nt], h00, bb.x, bb.y);
                mma8(acc[0][nt], h01, bb.z, bb.w);
                mma8(acc[1][nt], h10, bb.x, bb.y);
                mma8(acc[1][nt], h11, bb.z, bb.w);
            }
        }
    }

    // ---- epilogue: out[tok,:] += gate * (acc + b2) ----
#pragma unroll
    for (int nt = 0; nt < 8; nt++) {
        int col = (o2 * 8 + nt) * 8 + 2 * cc;
        float b2a = sm[B2_F + col], b2b = sm[B2_F + col + 1];
#pragma unroll
        for (int mi = 0; mi < 2; mi++) {
            float4 f = acc[mi][nt];
            int ra = (2 * p2 + mi) * 16 + gg;
            int rb = ra + 8;
            if (ra < rows) {
                float gt = s_gate[ra];
                float* ob = out + (size_t)s_tok[ra] * DM;
                atomicAdd(ob + col,     gt * (f.x + b2a));
                atomicAdd(ob + col + 1, gt * (f.y + b2b));
            }
            if (rb < rows) {
                float gt = s_gate[rb];
                float* ob = out + (size_t)s_tok[rb] * DM;
                atomicAdd(ob + col,     gt * (f.z + b2a));
                atomicAdd(ob + col + 1, gt * (f.w + b2b));
            }
        }
    }
}

// ---------------- launch ----------------
extern "C" void kernel_launch(void* const* d_in, const int* in_sizes, int n_in,
                              void* d_out, int out_size) {
    const float* v0   = (const float*)d_in[0];
    const float* v1   = (const float*)d_in[1];
    const float* v2   = (const float*)d_in[2];
    const float* rw   = (const float*)d_in[3];
    const float* keys = (const float*)d_in[4];
    const float* W1   = (const float*)d_in[5];
    const float* b1   = (const float*)d_in[6];
    const float* W2   = (const float*)d_in[7];
    const float* b2   = (const float*)d_in[8];
    float* out = (float*)d_out;

    cudaFuncSetAttribute(ffn_kernel, cudaFuncAttributeMaxDynamicSharedMemorySize,
                         SMEM_BYTES);

    cudaMemsetAsync(d_out, 0, (size_t)out_size * sizeof(float), 0);

    prep_kernel<<<1024, 256, 0, 0>>>(W1, W2);

    dim3 rgrid(N_TOK / 8, NVIEW, 1);
    router_kernel<<<rgrid, 256, 0, 0>>>(v0, v1, v2, rw, keys);

    dim3 fgrid(N_TOK / TM, NE, NVIEW);   // 128 x 16 x 3, most blocks exit early
    ffn_kernel<<<fgrid, 256, SMEM_BYTES, 0>>>(v0, v1, v2, b1, b2, out);
}

// round 7
// speedup vs baseline: 1.1278x; 1.1278x over previous
#include <cuda_runtime.h>
#include <math.h>
#include <cstdint>

#define N_TOK   8192
#define DM      256
#define NE      16
#define NVIEW   3
#define TOPK    4
#define HID     1024
#define TM      64

// ---- ffn smem layout (float indices) ----
#define XP_F    0           // Xperm A-frag order: 4mt x 32ks x 32lane x 4 = 16384
#define HP_F    16384       // Hperm A-frag order: 4mt x 32ks x 32lane x 4 = 16384
#define B1_F    32768       // 1024
#define B2_F    33792       // 256
#define TOK_F   34048       // 64 ints
#define GATE_F  34112       // 64
#define SMEM_FLOATS 34176
#define SMEM_BYTES  (SMEM_FLOATS * 4)    // 136704

// ---------------- device scratch ----------------
__device__ int   g_cnt [NVIEW * NE];
__device__ int   g_tok [NVIEW * NE * N_TOK];
__device__ float g_gate[NVIEW * NE * N_TOK];
__device__ float g_w1p [NE * DM * HID];   // W1, tf32-rounded, B-frag order
__device__ float g_w2p [NE * HID * DM];   // W2, tf32-rounded, B-frag order

// ---------------- helpers ----------------
__device__ __forceinline__ float tf32r(float x) {
    asm("cvt.rna.tf32.f32 %0, %1;" : "=f"(x) : "f"(x));
    return x;
}
__device__ __forceinline__ float4 tf32r4(float4 v) {
    v.x = tf32r(v.x); v.y = tf32r(v.y); v.z = tf32r(v.z); v.w = tf32r(v.w);
    return v;
}
__device__ __forceinline__ float d4(float4 a, float4 b) {
    return a.x * b.x + a.y * b.y + a.z * b.z + a.w * b.w;
}
__device__ __forceinline__ float wredsum(float x) {
#pragma unroll
    for (int o = 16; o > 0; o >>= 1) x += __shfl_xor_sync(0xffffffffu, x, o);
    return x;
}
__device__ __forceinline__ float gelu_exact(float x) {
    return 0.5f * x * (1.0f + erff(x * 0.70710678118654752440f));
}
// m16n8k8 tf32 mma: D += A*B
__device__ __forceinline__ void mma8(float4& d, const uint4& a,
                                     uint32_t b0, uint32_t b1) {
    asm volatile(
        "mma.sync.aligned.m16n8k8.row.col.f32.tf32.tf32.f32 "
        "{%0,%1,%2,%3}, {%4,%5,%6,%7}, {%8,%9}, {%0,%1,%2,%3};"
        : "+f"(d.x), "+f"(d.y), "+f"(d.z), "+f"(d.w)
        : "r"(a.x), "r"(a.y), "r"(a.z), "r"(a.w), "r"(b0), "r"(b1));
}

// ---------------- kernel 0: prep (unchanged) ----------------
__global__ void prep_kernel(const float* __restrict__ W1,
                            const float* __restrict__ W2) {
    __shared__ float s[256 * 36];
    int tid = threadIdx.x, b = blockIdx.x;
    if (b == 0 && tid < NVIEW * NE) g_cnt[tid] = 0;
    if (b < 512) {
        int e = b >> 5, jc = b & 31;
        for (int i = tid; i < 2048; i += 256) {
            int d = i >> 3, j4 = i & 7;
            float4 v = ((const float4*)(W1 + ((size_t)e * DM + d) * HID + jc * 32))[j4];
            *(float4*)&s[d * 36 + j4 * 4] = tf32r4(v);
        }
        __syncthreads();
        float4* dst = (float4*)g_w1p + (size_t)(e * 32 + jc) * 2048;
        for (int o = tid; o < 2048; o += 256) {
            int nt = o >> 9, kp = (o >> 5) & 15, ln = o & 31;
            int tig = ln & 3, g = ln >> 2;
            int jl = nt * 8 + g;
            float4 v;
            v.x = s[(16 * kp + tig) * 36 + jl];
            v.y = s[(16 * kp + tig + 4) * 36 + jl];
            v.z = s[(16 * kp + 8 + tig) * 36 + jl];
            v.w = s[(16 * kp + 8 + tig + 4) * 36 + jl];
            dst[o] = v;
        }
    } else {
        int e = (b - 512) >> 5, jc = (b - 512) & 31;
        for (int i = tid; i < 2048; i += 256) {
            int rl = i >> 6, n4 = i & 63;
            float4 v = ((const float4*)(W2 + ((size_t)e * HID + jc * 32 + rl) * DM))[n4];
            *(float4*)&s[rl * 260 + n4 * 4] = tf32r4(v);
        }
        __syncthreads();
        float4* dst = (float4*)g_w2p + (size_t)(e * 32 + jc) * 2048;
        for (int o = tid; o < 2048; o += 256) {
            int nt = o >> 6, kp = (o >> 5) & 1, ln = o & 31;
            int tig = ln & 3, g = ln >> 2;
            int n = nt * 8 + g;
            float4 v;
            v.x = s[(16 * kp + tig) * 260 + n];
            v.y = s[(16 * kp + tig + 4) * 260 + n];
            v.z = s[(16 * kp + 8 + tig) * 260 + n];
            v.w = s[(16 * kp + 8 + tig + 4) * 260 + n];
            dst[o] = v;
        }
    }
}

// ---------------- kernel 1: router (bit-exact fp32 sequence, unchanged) ------
__global__ void router_kernel(const float* __restrict__ v0,
                              const float* __restrict__ v1,
                              const float* __restrict__ v2,
                              const float* __restrict__ rw,
                              const float* __restrict__ keys) {
    int vi   = blockIdx.y;
    int warp = threadIdx.x >> 5;
    int lane = threadIdx.x & 31;
    int tok  = blockIdx.x * 8 + warp;
    if (tok >= N_TOK) return;

    const float* vbase = (vi == 0) ? v0 : ((vi == 1) ? v1 : v2);
    const float* v = vbase + tok * DM;

    float4 a = ((const float4*)v)[lane];
    float4 b = ((const float4*)v)[lane + 32];

    float vv = wredsum(d4(a, a) + d4(b, b));

    const float* rwv = rw + (size_t)vi * NE * DM;
    float lg[NE];
#pragma unroll
    for (int e = 0; e < NE; e++) {
        const float4* kp = (const float4*)(keys + e * DM);
        const float4* rp = (const float4*)(rwv + e * DM);
        float4 k1 = kp[lane], k2 = kp[lane + 32];
        float4 r1 = rp[lane], r2 = rp[lane + 32];
        float dk = wredsum(d4(a, k1) + d4(b, k2));
        float dr = wredsum(d4(a, r1) + d4(b, r2));
        float kk = wredsum(d4(k1, k1) + d4(k2, k2));
        float sq = (vv + kk) - 2.0f * dk;
        lg[e] = (-sq) + dr;
    }

    if (lane == 0) {
        unsigned chosen = 0;
        float tv[TOPK];
        int   ti[TOPK];
#pragma unroll
        for (int k = 0; k < TOPK; k++) {
            float m = -1e30f; int mi = 0;
#pragma unroll
            for (int e = 0; e < NE; e++) {
                if (!((chosen >> e) & 1u) && lg[e] > m) { m = lg[e]; mi = e; }
            }
            tv[k] = m; ti[k] = mi; chosen |= (1u << mi);
        }
        float s = 0.f;
        float ex[TOPK];
#pragma unroll
        for (int k = 0; k < TOPK; k++) { ex[k] = expf(tv[k] - tv[0]); s += ex[k]; }
        float inv = 1.0f / s;
#pragma unroll
        for (int k = 0; k < TOPK; k++) {
            int ge  = vi * NE + ti[k];
            int pos = atomicAdd(&g_cnt[ge], 1);
            g_tok [ge * N_TOK + pos] = tok;
            g_gate[ge * N_TOK + pos] = ex[k] * inv;
        }
    }
}

// ---------------- kernel 2: grouped FFN, big warp tiles, B from L2 ----------
extern "C" __global__ void __launch_bounds__(256, 1)
ffn_kernel(const float* __restrict__ v0, const float* __restrict__ v1,
           const float* __restrict__ v2,
           const float* __restrict__ b1, const float* __restrict__ b2,
           float* __restrict__ out) {
    extern __shared__ float sm[];
    int tid = threadIdx.x, wid = tid >> 5, lane = tid & 31;
    int vi = blockIdx.z, e = blockIdx.y, g0 = vi * NE + e;
    int cnt = g_cnt[g0];
    int t0 = blockIdx.x * TM;
    if (t0 >= cnt) return;
    int rows = min(TM, cnt - t0);

    int*   s_tok  = (int*)&sm[TOK_F];
    float* s_gate = &sm[GATE_F];
    if (tid < TM) {
        int idx = t0 + tid;
        s_tok [tid] = (idx < cnt) ? g_tok [g0 * N_TOK + idx] : 0;
        s_gate[tid] = (idx < cnt) ? g_gate[g0 * N_TOK + idx] : 0.0f;
    }
    for (int i = tid; i < HID; i += 256) sm[B1_F + i] = b1[(size_t)e * HID + i];
    for (int i = tid; i < DM;  i += 256) sm[B2_F + i] = b2[(size_t)e * DM + i];
    __syncthreads();

    const float* V = (vi == 0) ? v0 : ((vi == 1) ? v1 : v2);

    // ---- gather X -> A-fragment-permuted smem (tf32-rna) ----
    for (int i = tid; i < TM * 64; i += 256) {
        int r = i >> 6, c4 = i & 63;
        float4 v = make_float4(0.f, 0.f, 0.f, 0.f);
        if (r < rows) v = tf32r4(((const float4*)(V + (size_t)s_tok[r] * DM))[c4]);
        int mt = r >> 4, pair = (r >> 3) & 1, gg = r & 7;
        int ks = c4 >> 1, q = pair + 2 * (c4 & 1);
        int base = ((mt * 32 + ks) * 32 + gg * 4) * 4 + q;
        sm[XP_F + base     ] = v.x;
        sm[XP_F + base + 4 ] = v.y;
        sm[XP_F + base + 8 ] = v.z;
        sm[XP_F + base + 12] = v.w;
    }
    __syncthreads();

    const uint4* XP  = (const uint4*)&sm[XP_F];
    const uint4* HPl = (const uint4*)&sm[HP_F];
    const uint4* W1P = (const uint4*)g_w1p + (size_t)(e * 32) * 2048;
    const uint4* W2P = (const uint4*)g_w2p + (size_t)(e * 32) * 2048;
    const int gg = lane >> 2, cc = lane & 3;

    float4 acc[4][4];   // GEMM2 output: warp tile m64 x n32 (mt x ntl)
#pragma unroll
    for (int i = 0; i < 4; i++)
#pragma unroll
        for (int j = 0; j < 4; j++) acc[i][j] = make_float4(0.f, 0.f, 0.f, 0.f);

#pragma unroll 1
    for (int sc = 0; sc < 4; sc++) {
        // ================= GEMM1: warp wid owns chunk jc (n32 of W1) =========
        int jc = sc * 8 + wid;
        float4 a1[4][4];   // H pre-activation: m64 x n32
#pragma unroll
        for (int i = 0; i < 4; i++)
#pragma unroll
            for (int j = 0; j < 4; j++) a1[i][j] = make_float4(0.f, 0.f, 0.f, 0.f);
        {
            const uint4* W1j = W1P + (size_t)jc * 2048 + lane;
            uint4 bbuf[2][4];
#pragma unroll
            for (int nt = 0; nt < 4; nt++) {
                bbuf[0][nt] = W1j[nt * 512];
                bbuf[1][nt] = W1j[nt * 512 + 32];
            }
#pragma unroll
            for (int kp = 0; kp < 16; kp++) {
                uint4 alo[4], ahi[4];
#pragma unroll
                for (int mt = 0; mt < 4; mt++) {
                    alo[mt] = XP[(mt * 32 + 2 * kp) * 32 + lane];
                    ahi[mt] = XP[(mt * 32 + 2 * kp + 1) * 32 + lane];
                }
                uint4 bc[4];
#pragma unroll
                for (int nt = 0; nt < 4; nt++) bc[nt] = bbuf[kp & 1][nt];
                if (kp + 2 < 16) {
#pragma unroll
                    for (int nt = 0; nt < 4; nt++)
                        bbuf[kp & 1][nt] = W1j[nt * 512 + (kp + 2) * 32];
                }
#pragma unroll
                for (int mt = 0; mt < 4; mt++)
#pragma unroll
                    for (int nt = 0; nt < 4; nt++) {
                        mma8(a1[mt][nt], alo[mt], bc[nt].x, bc[nt].y);
                        mma8(a1[mt][nt], ahi[mt], bc[nt].z, bc[nt].w);
                    }
            }
        }

        // ---- bias + exact GELU -> Hperm (A-frag order, tf32-rna) ----
#pragma unroll
        for (int mt = 0; mt < 4; mt++)
#pragma unroll
            for (int nt = 0; nt < 4; nt++) {
                int c0 = jc * 32 + nt * 8 + 2 * cc;
                float bx = sm[B1_F + c0];
                float by = sm[B1_F + c0 + 1];
                float4 v = a1[mt][nt];
                int ks = wid * 4 + nt;   // k8-step within superchunk (0..31)
                int base = ((mt * 32 + ks) * 32 + gg * 4) * 4
                         + 2 * (cc >> 1) + 8 * (cc & 1);
                sm[HP_F + base    ] = tf32r(gelu_exact(v.x + bx));
                sm[HP_F + base + 4] = tf32r(gelu_exact(v.y + by));
                sm[HP_F + base + 1] = tf32r(gelu_exact(v.z + bx));
                sm[HP_F + base + 5] = tf32r(gelu_exact(v.w + by));
            }
        __syncthreads();   // H complete

        // ================= GEMM2: warp wid owns n32 of DM, K = 256 ===========
        {
            uint4 bbuf[2][4];
#pragma unroll
            for (int nt = 0; nt < 4; nt++) {
                // kp=0: jc2 = sc*8, kp_in=0 ; kp=1: jc2 = sc*8, kp_in=1
                bbuf[0][nt] = W2P[(size_t)(sc * 8) * 2048 + (wid * 4 + nt) * 64 + lane];
                bbuf[1][nt] = W2P[(size_t)(sc * 8) * 2048 + (wid * 4 + nt) * 64 + 32 + lane];
            }
#pragma unroll
            for (int kp = 0; kp < 16; kp++) {
                uint4 hlo[4], hhi[4];
#pragma unroll
                for (int mt = 0; mt < 4; mt++) {
                    hlo[mt] = HPl[(mt * 32 + 2 * kp) * 32 + lane];
                    hhi[mt] = HPl[(mt * 32 + 2 * kp + 1) * 32 + lane];
                }
                uint4 bc[4];
#pragma unroll
                for (int nt = 0; nt < 4; nt++) bc[nt] = bbuf[kp & 1][nt];
                if (kp + 2 < 16) {
                    int kq = kp + 2;
                    size_t jb = (size_t)(sc * 8 + (kq >> 1)) * 2048 + (kq & 1) * 32;
#pragma unroll
                    for (int nt = 0; nt < 4; nt++)
                        bbuf[kp & 1][nt] = W2P[jb + (wid * 4 + nt) * 64 + lane];
                }
#pragma unroll
                for (int mt = 0; mt < 4; mt++)
#pragma unroll
                    for (int nt = 0; nt < 4; nt++) {
                        mma8(acc[mt][nt], hlo[mt], bc[nt].x, bc[nt].y);
                        mma8(acc[mt][nt], hhi[mt], bc[nt].z, bc[nt].w);
                    }
            }
        }
        __syncthreads();   // GEMM2 done reading H; next sc may overwrite
    }

    // ---- epilogue: out[tok,:] += gate * (acc + b2) ----
#pragma unroll
    for (int nt = 0; nt < 4; nt++) {
        int col = (wid * 4 + nt) * 8 + 2 * cc;
        float b2a = sm[B2_F + col], b2b = sm[B2_F + col + 1];
#pragma unroll
        for (int mt = 0; mt < 4; mt++) {
            float4 f = acc[mt][nt];
            int ra = mt * 16 + gg;
            int rb = ra + 8;
            if (ra < rows) {
                float gt = s_gate[ra];
                float* ob = out + (size_t)s_tok[ra] * DM;
                atomicAdd(ob + col,     gt * (f.x + b2a));
                atomicAdd(ob + col + 1, gt * (f.y + b2b));
            }
            if (rb < rows) {
                float gt = s_gate[rb];
                float* ob = out + (size_t)s_tok[rb] * DM;
                atomicAdd(ob + col,     gt * (f.z + b2a));
                atomicAdd(ob + col + 1, gt * (f.w + b2b));
            }
        }
    }
}

// ---------------- launch ----------------
extern "C" void kernel_launch(void* const* d_in, const int* in_sizes, int n_in,
                              void* d_out, int out_size) {
    const float* v0   = (const float*)d_in[0];
    const float* v1   = (const float*)d_in[1];
    const float* v2   = (const float*)d_in[2];
    const float* rw   = (const float*)d_in[3];
    const float* keys = (const float*)d_in[4];
    const float* W1   = (const float*)d_in[5];
    const float* b1   = (const float*)d_in[6];
    const float* W2   = (const float*)d_in[7];
    const float* b2   = (const float*)d_in[8];
    float* out = (float*)d_out;

    cudaFuncSetAttribute(ffn_kernel, cudaFuncAttributeMaxDynamicSharedMemorySize,
                         SMEM_BYTES);

    cudaMemsetAsync(d_out, 0, (size_t)out_size * sizeof(float), 0);

    prep_kernel<<<1024, 256, 0, 0>>>(W1, W2);

    dim3 rgrid(N_TOK / 8, NVIEW, 1);
    router_kernel<<<rgrid, 256, 0, 0>>>(v0, v1, v2, rw, keys);

    dim3 fgrid(N_TOK / TM, NE, NVIEW);   // 128 x 16 x 3, most blocks exit early
    ffn_kernel<<<fgrid, 256, SMEM_BYTES, 0>>>(v0, v1, v2, b1, b2, out);
}

// round 8
// speedup vs baseline: 1.7557x; 1.5568x over previous
#include <cuda_runtime.h>
#include <math.h>
#include <cstdint>

#define N_TOK   8192
#define DM      256
#define NE      16
#define NVIEW   3
#define TOPK    4
#define HID     1024
#define TM      64

// ---- ffn smem layout (float indices) ----
#define XP_F    0           // Xperm A-frag order: [4mt][32ks][32lane][4] = 16384
#define HP_F    16384       // Hperm A-frag order: [4mt][8ks][32lane][4] = 4096
#define B1_F    20480       // 1024
#define B2_F    21504       // 256
#define TOK_F   21760       // 64 ints
#define GATE_F  21824       // 64
#define SMEM_FLOATS 21888
#define SMEM_BYTES  (SMEM_FLOATS * 4)    // 87552 -> 2 blocks/SM

// ---------------- device scratch ----------------
__device__ int   g_cnt [NVIEW * NE];
__device__ int   g_tok [NVIEW * NE * N_TOK];
__device__ float g_gate[NVIEW * NE * N_TOK];
__device__ float g_w1p [NE * DM * HID];   // W1, tf32-rounded, B-frag order
__device__ float g_w2p [NE * HID * DM];   // W2, tf32-rounded, B-frag order

// ---------------- helpers ----------------
__device__ __forceinline__ float tf32r(float x) {
    asm("cvt.rna.tf32.f32 %0, %1;" : "=f"(x) : "f"(x));
    return x;
}
__device__ __forceinline__ float4 tf32r4(float4 v) {
    v.x = tf32r(v.x); v.y = tf32r(v.y); v.z = tf32r(v.z); v.w = tf32r(v.w);
    return v;
}
__device__ __forceinline__ float d4(float4 a, float4 b) {
    return a.x * b.x + a.y * b.y + a.z * b.z + a.w * b.w;
}
__device__ __forceinline__ float wredsum(float x) {
#pragma unroll
    for (int o = 16; o > 0; o >>= 1) x += __shfl_xor_sync(0xffffffffu, x, o);
    return x;
}
__device__ __forceinline__ float gelu_exact(float x) {
    return 0.5f * x * (1.0f + erff(x * 0.70710678118654752440f));
}
// m16n8k8 tf32 mma: D += A*B
__device__ __forceinline__ void mma8(float4& d, const uint4& a,
                                     uint32_t b0, uint32_t b1) {
    asm volatile(
        "mma.sync.aligned.m16n8k8.row.col.f32.tf32.tf32.f32 "
        "{%0,%1,%2,%3}, {%4,%5,%6,%7}, {%8,%9}, {%0,%1,%2,%3};"
        : "+f"(d.x), "+f"(d.y), "+f"(d.z), "+f"(d.w)
        : "r"(a.x), "r"(a.y), "r"(a.z), "r"(a.w), "r"(b0), "r"(b1));
}
__device__ __forceinline__ void red2(float* p, float a, float b) {
    asm volatile("red.global.add.v2.f32 [%0], {%1, %2};"
                 :: "l"(p), "f"(a), "f"(b) : "memory");
}

// ---------------- kernel 0: prep (round+permute weights, zero cnt & out) ----
__global__ void prep_kernel(const float* __restrict__ W1,
                            const float* __restrict__ W2,
                            float* __restrict__ out) {
    __shared__ float s[256 * 36];
    int tid = threadIdx.x, b = blockIdx.x;
    if (b == 0 && tid < NVIEW * NE) g_cnt[tid] = 0;
    {   // zero out: 2,097,152 floats = 524288 float4 over 1024 blocks
        float4* o4 = (float4*)out;
        int zb = b * 512 + tid;
        o4[zb]       = make_float4(0.f, 0.f, 0.f, 0.f);
        o4[zb + 256] = make_float4(0.f, 0.f, 0.f, 0.f);
    }
    if (b < 512) {
        int e = b >> 5, jc = b & 31;
        for (int i = tid; i < 2048; i += 256) {
            int d = i >> 3, j4 = i & 7;
            float4 v = ((const float4*)(W1 + ((size_t)e * DM + d) * HID + jc * 32))[j4];
            *(float4*)&s[d * 36 + j4 * 4] = tf32r4(v);
        }
        __syncthreads();
        float4* dst = (float4*)g_w1p + (size_t)(e * 32 + jc) * 2048;
        for (int o = tid; o < 2048; o += 256) {
            int nt = o >> 9, kp = (o >> 5) & 15, ln = o & 31;
            int tig = ln & 3, g = ln >> 2;
            int jl = nt * 8 + g;
            float4 v;
            v.x = s[(16 * kp + tig) * 36 + jl];
            v.y = s[(16 * kp + tig + 4) * 36 + jl];
            v.z = s[(16 * kp + 8 + tig) * 36 + jl];
            v.w = s[(16 * kp + 8 + tig + 4) * 36 + jl];
            dst[o] = v;
        }
    } else {
        int e = (b - 512) >> 5, jc = (b - 512) & 31;
        for (int i = tid; i < 2048; i += 256) {
            int rl = i >> 6, n4 = i & 63;
            float4 v = ((const float4*)(W2 + ((size_t)e * HID + jc * 32 + rl) * DM))[n4];
            *(float4*)&s[rl * 260 + n4 * 4] = tf32r4(v);
        }
        __syncthreads();
        float4* dst = (float4*)g_w2p + (size_t)(e * 32 + jc) * 2048;
        for (int o = tid; o < 2048; o += 256) {
            int nt = o >> 6, kp = (o >> 5) & 1, ln = o & 31;
            int tig = ln & 3, g = ln >> 2;
            int n = nt * 8 + g;
            float4 v;
            v.x = s[(16 * kp + tig) * 260 + n];
            v.y = s[(16 * kp + tig + 4) * 260 + n];
            v.z = s[(16 * kp + 8 + tig) * 260 + n];
            v.w = s[(16 * kp + 8 + tig + 4) * 260 + n];
            dst[o] = v;
        }
    }
}

// ---------------- kernel 1: router (bit-exact fp32 sequence, unchanged) ------
__global__ void router_kernel(const float* __restrict__ v0,
                              const float* __restrict__ v1,
                              const float* __restrict__ v2,
                              const float* __restrict__ rw,
                              const float* __restrict__ keys) {
    int vi   = blockIdx.y;
    int warp = threadIdx.x >> 5;
    int lane = threadIdx.x & 31;
    int tok  = blockIdx.x * 8 + warp;
    if (tok >= N_TOK) return;

    const float* vbase = (vi == 0) ? v0 : ((vi == 1) ? v1 : v2);
    const float* v = vbase + tok * DM;

    float4 a = ((const float4*)v)[lane];
    float4 b = ((const float4*)v)[lane + 32];

    float vv = wredsum(d4(a, a) + d4(b, b));

    const float* rwv = rw + (size_t)vi * NE * DM;
    float lg[NE];
#pragma unroll
    for (int e = 0; e < NE; e++) {
        const float4* kp = (const float4*)(keys + e * DM);
        const float4* rp = (const float4*)(rwv + e * DM);
        float4 k1 = kp[lane], k2 = kp[lane + 32];
        float4 r1 = rp[lane], r2 = rp[lane + 32];
        float dk = wredsum(d4(a, k1) + d4(b, k2));
        float dr = wredsum(d4(a, r1) + d4(b, r2));
        float kk = wredsum(d4(k1, k1) + d4(k2, k2));
        float sq = (vv + kk) - 2.0f * dk;
        lg[e] = (-sq) + dr;
    }

    if (lane == 0) {
        unsigned chosen = 0;
        float tv[TOPK];
        int   ti[TOPK];
#pragma unroll
        for (int k = 0; k < TOPK; k++) {
            float m = -1e30f; int mi = 0;
#pragma unroll
            for (int e = 0; e < NE; e++) {
                if (!((chosen >> e) & 1u) && lg[e] > m) { m = lg[e]; mi = e; }
            }
            tv[k] = m; ti[k] = mi; chosen |= (1u << mi);
        }
        float s = 0.f;
        float ex[TOPK];
#pragma unroll
        for (int k = 0; k < TOPK; k++) { ex[k] = expf(tv[k] - tv[0]); s += ex[k]; }
        float inv = 1.0f / s;
#pragma unroll
        for (int k = 0; k < TOPK; k++) {
            int ge  = vi * NE + ti[k];
            int pos = atomicAdd(&g_cnt[ge], 1);
            g_tok [ge * N_TOK + pos] = tok;
            g_gate[ge * N_TOK + pos] = ex[k] * inv;
        }
    }
}

// ---------------- kernel 2: grouped FFN, occupancy-2 balanced tiling --------
extern "C" __global__ void __launch_bounds__(256, 2)
ffn_kernel(const float* __restrict__ v0, const float* __restrict__ v1,
           const float* __restrict__ v2,
           const float* __restrict__ b1, const float* __restrict__ b2,
           float* __restrict__ out) {
    extern __shared__ float sm[];
    int tid = threadIdx.x, wid = tid >> 5, lane = tid & 31;
    int vi = blockIdx.z, e = blockIdx.y, g0 = vi * NE + e;
    int cnt = g_cnt[g0];
    int t0 = blockIdx.x * TM;
    if (t0 >= cnt) return;
    int rows = min(TM, cnt - t0);

    int*   s_tok  = (int*)&sm[TOK_F];
    float* s_gate = &sm[GATE_F];
    if (tid < TM) {
        int idx = t0 + tid;
        s_tok [tid] = (idx < cnt) ? g_tok [g0 * N_TOK + idx] : 0;
        s_gate[tid] = (idx < cnt) ? g_gate[g0 * N_TOK + idx] : 0.0f;
    }
    for (int i = tid; i < HID; i += 256) sm[B1_F + i] = b1[(size_t)e * HID + i];
    for (int i = tid; i < DM;  i += 256) sm[B2_F + i] = b2[(size_t)e * DM + i];
    __syncthreads();

    const float* V = (vi == 0) ? v0 : ((vi == 1) ? v1 : v2);

    // ---- gather X -> A-fragment-permuted smem (tf32-rna) ----
    for (int i = tid; i < TM * 64; i += 256) {
        int r = i >> 6, c4 = i & 63;
        float4 v = make_float4(0.f, 0.f, 0.f, 0.f);
        if (r < rows) v = tf32r4(((const float4*)(V + (size_t)s_tok[r] * DM))[c4]);
        int mt = r >> 4, pair = (r >> 3) & 1, gg2 = r & 7;
        int ks = c4 >> 1, q = pair + 2 * (c4 & 1);
        int base = ((mt * 32 + ks) * 32 + gg2 * 4) * 4 + q;
        sm[XP_F + base     ] = v.x;
        sm[XP_F + base + 4 ] = v.y;
        sm[XP_F + base + 8 ] = v.z;
        sm[XP_F + base + 12] = v.w;
    }
    __syncthreads();

    const uint4* XP  = (const uint4*)&sm[XP_F];
    const uint4* HPl = (const uint4*)&sm[HP_F];
    const uint4* W1P = (const uint4*)g_w1p + (size_t)(e * 32) * 2048;
    const uint4* W2P = (const uint4*)g_w2p + (size_t)(e * 32) * 2048;
    const int gg = lane >> 2, cc = lane & 3;
    const int m1 = wid & 1, n1 = (wid >> 1) & 1, ch = wid >> 2;   // GEMM1 roles

    float4 acc[4][4];   // GEMM2: warp tile m64 x n32
#pragma unroll
    for (int i = 0; i < 4; i++)
#pragma unroll
        for (int j = 0; j < 4; j++) acc[i][j] = make_float4(0.f, 0.f, 0.f, 0.f);

#pragma unroll 1
    for (int sc = 0; sc < 16; sc++) {
        int jc = sc * 2 + ch;          // 32-col W1 chunk owned by this warp pair
        // ================= GEMM1: warp tile m32 x n16, K = 256 ===============
        float4 a1[2][2];
#pragma unroll
        for (int i = 0; i < 2; i++)
#pragma unroll
            for (int j = 0; j < 2; j++) a1[i][j] = make_float4(0.f, 0.f, 0.f, 0.f);
        {
            const uint4* W1j = W1P + (size_t)jc * 2048 + lane;
            const int nb0 = (n1 * 2) * 512, nb1 = (n1 * 2 + 1) * 512;
            uint4 bb[2][2];
            bb[0][0] = W1j[nb0];      bb[0][1] = W1j[nb1];
            bb[1][0] = W1j[nb0 + 32]; bb[1][1] = W1j[nb1 + 32];
#pragma unroll
            for (int kp = 0; kp < 16; kp++) {
                uint4 bc0 = bb[kp & 1][0], bc1 = bb[kp & 1][1];
                if (kp + 2 < 16) {
                    bb[kp & 1][0] = W1j[nb0 + (kp + 2) * 32];
                    bb[kp & 1][1] = W1j[nb1 + (kp + 2) * 32];
                }
#pragma unroll
                for (int mt2 = 0; mt2 < 2; mt2++) {
                    int mt = 2 * m1 + mt2;
                    uint4 alo = XP[(mt * 32 + 2 * kp) * 32 + lane];
                    uint4 ahi = XP[(mt * 32 + 2 * kp + 1) * 32 + lane];
                    mma8(a1[mt2][0], alo, bc0.x, bc0.y);
                    mma8(a1[mt2][0], ahi, bc0.z, bc0.w);
                    mma8(a1[mt2][1], alo, bc1.x, bc1.y);
                    mma8(a1[mt2][1], ahi, bc1.z, bc1.w);
                }
            }
        }
        // ---- bias + exact GELU -> Hperm (A-frag order, tf32-rna) ----
#pragma unroll
        for (int mt2 = 0; mt2 < 2; mt2++) {
            int mt = 2 * m1 + mt2;
#pragma unroll
            for (int t = 0; t < 2; t++) {
                int nt = n1 * 2 + t;
                int ks = ch * 4 + nt;            // k8 index within superchunk
                int c0 = jc * 32 + nt * 8 + 2 * cc;
                float bx = sm[B1_F + c0];
                float by = sm[B1_F + c0 + 1];
                float4 v = a1[mt2][t];
                int base = ((mt * 8 + ks) * 32 + gg * 4) * 4
                         + 2 * (cc >> 1) + 8 * (cc & 1);
                sm[HP_F + base    ] = tf32r(gelu_exact(v.x + bx));
                sm[HP_F + base + 4] = tf32r(gelu_exact(v.y + by));
                sm[HP_F + base + 1] = tf32r(gelu_exact(v.z + bx));
                sm[HP_F + base + 5] = tf32r(gelu_exact(v.w + by));
            }
        }
        __syncthreads();   // H ready

        // ================= GEMM2: warp tile m64 x n32, K = 64 ================
        {
            const int nb = wid * 4;
            uint4 wb[2][4];
#pragma unroll
            for (int nt = 0; nt < 4; nt++) {
                wb[0][nt] = W2P[(size_t)(sc * 2) * 2048 + (nb + nt) * 64 + lane];
                wb[1][nt] = W2P[(size_t)(sc * 2) * 2048 + (nb + nt) * 64 + 32 + lane];
            }
#pragma unroll
            for (int kq = 0; kq < 4; kq++) {
                uint4 bc[4];
#pragma unroll
                for (int nt = 0; nt < 4; nt++) bc[nt] = wb[kq & 1][nt];
                if (kq + 2 < 4) {
                    size_t jb = (size_t)(sc * 2 + ((kq + 2) >> 1)) * 2048
                              + ((kq + 2) & 1) * 32;
#pragma unroll
                    for (int nt = 0; nt < 4; nt++)
                        wb[kq & 1][nt] = W2P[jb + (nb + nt) * 64 + lane];
                }
#pragma unroll
                for (int mt = 0; mt < 4; mt++) {
                    uint4 hlo = HPl[(mt * 8 + 2 * kq) * 32 + lane];
                    uint4 hhi = HPl[(mt * 8 + 2 * kq + 1) * 32 + lane];
#pragma unroll
                    for (int nt = 0; nt < 4; nt++) {
                        mma8(acc[mt][nt], hlo, bc[nt].x, bc[nt].y);
                        mma8(acc[mt][nt], hhi, bc[nt].z, bc[nt].w);
                    }
                }
            }
        }
        __syncthreads();   // GEMM2 done reading H; next sc may overwrite
    }

    // ---- epilogue: out[tok,:] += gate * (acc + b2), vector red ----
#pragma unroll
    for (int nt = 0; nt < 4; nt++) {
        int col = (wid * 4 + nt) * 8 + 2 * cc;
        float b2a = sm[B2_F + col], b2b = sm[B2_F + col + 1];
#pragma unroll
        for (int mt = 0; mt < 4; mt++) {
            float4 f = acc[mt][nt];
            int ra = mt * 16 + gg;
            int rb = ra + 8;
            if (ra < rows) {
                float gt = s_gate[ra];
                red2(out + (size_t)s_tok[ra] * DM + col,
                     gt * (f.x + b2a), gt * (f.y + b2b));
            }
            if (rb < rows) {
                float gt = s_gate[rb];
                red2(out + (size_t)s_tok[rb] * DM + col,
                     gt * (f.z + b2a), gt * (f.w + b2b));
            }
        }
    }
}

// ---------------- launch ----------------
extern "C" void kernel_launch(void* const* d_in, const int* in_sizes, int n_in,
                              void* d_out, int out_size) {
    const float* v0   = (const float*)d_in[0];
    const float* v1   = (const float*)d_in[1];
    const float* v2   = (const float*)d_in[2];
    const float* rw   = (const float*)d_in[3];
    const float* keys = (const float*)d_in[4];
    const float* W1   = (const float*)d_in[5];
    const float* b1   = (const float*)d_in[6];
    const float* W2   = (const float*)d_in[7];
    const float* b2   = (const float*)d_in[8];
    float* out = (float*)d_out;

    cudaFuncSetAttribute(ffn_kernel, cudaFuncAttributeMaxDynamicSharedMemorySize,
                         SMEM_BYTES);

    prep_kernel<<<1024, 256, 0, 0>>>(W1, W2, out);

    dim3 rgrid(N_TOK / 8, NVIEW, 1);
    router_kernel<<<rgrid, 256, 0, 0>>>(v0, v1, v2, rw, keys);

    dim3 fgrid(N_TOK / TM, NE, NVIEW);   // 128 x 16 x 3, most blocks exit early
    ffn_kernel<<<fgrid, 256, SMEM_BYTES, 0>>>(v0, v1, v2, b1, b2, out);
}